// round 15
// baseline (speedup 1.0000x reference)
#include <cuda_runtime.h>
#include <cuda_fp16.h>
#include <cstdint>

#define BATCH   4096
#define DIM     16
#define NRULES  1024
#define NCLS    10
#define IEXT    17
#define NCOLS   170
#define KSPLIT  4
#define KTOT    2048                 // 2 passes x 1024 (ah*bh, ah*bl)
#define KLOC    (KTOT / KSPLIT)      // 512
#define NCH     (KLOC / 64)          // 8

// single TU-wide dynamic smem symbol
extern __shared__ char dyn_smem[];

// ---------------- static device scratch ----------------
__device__ __half g_Af[BATCH * NRULES];     // norm_fs fp16 (hi only)
__device__ __half g_Bc[192 * 2048];         // [n][ Bh(1024) | Bl(1024) ]
__device__ float  g_Yp[KSPLIT * BATCH * NCLS];  // per-ks partial y (640KB)

// ---------------- helpers ----------------
__device__ __forceinline__ uint32_t smem_u32(const void* p) {
    uint32_t a;
    asm("{ .reg .u64 t; cvta.to.shared.u64 t, %1; cvt.u32.u64 %0, t; }" : "=r"(a) : "l"(p));
    return a;
}
#define SWZ128(o) ((o) ^ (((o) >> 3) & 0x70))

#define CP_ASYNC16(dst, src) \
    asm volatile("cp.async.cg.shared.global [%0], [%1], 16;" :: "r"(dst), "l"(src))
#define CP_COMMIT() asm volatile("cp.async.commit_group;" ::: "memory")
#define CP_WAIT1()  asm volatile("cp.async.wait_group 1;" ::: "memory")
#define CP_WAIT0()  asm volatile("cp.async.wait_group 0;" ::: "memory")

#define LDSM_X4(r0, r1, r2, r3, addr)                                        \
    asm volatile("ldmatrix.sync.aligned.m8n8.x4.shared.b16 {%0,%1,%2,%3}, [%4];" \
        : "=r"(r0), "=r"(r1), "=r"(r2), "=r"(r3) : "r"(addr))

__device__ __forceinline__ void mma16816(float* c, const uint32_t* a, const uint32_t* b) {
    asm volatile(
        "mma.sync.aligned.m16n8k16.row.col.f32.f16.f16.f32 "
        "{%0,%1,%2,%3}, {%4,%5,%6,%7}, {%8,%9}, {%0,%1,%2,%3};"
        : "+f"(c[0]), "+f"(c[1]), "+f"(c[2]), "+f"(c[3])
        : "r"(a[0]), "r"(a[1]), "r"(a[2]), "r"(a[3]), "r"(b[0]), "r"(b[1]));
}

// compile-time-indexed contraction: y[(G0+q)%10] += xr[(G0+q)/10]*tr[q]
template<int G0, int NN>
__device__ __forceinline__ void epi_contract(const float* __restrict__ xr,
                                             const float* __restrict__ tr,
                                             float* __restrict__ y)
{
#pragma unroll
    for (int q = 0; q < NN; q++)
        y[(G0 + q) % 10] += xr[(G0 + q) / 10] * tr[q];
}

// =====================================================================
// k_fire: fused EVERYTHING-stage-1 kernel. grid = 128 CTAs x 512 thr.
//  - CTAs 0..15 additionally build g_Bc (conseq transpose hi|lo + pad)
//  - every CTA writes its 32 rows of x_ext
//  - A tile (Zh hi|lo fp16) computed in-CTA from x/centers/widths
//  - B tiles (one-hot fp16) computed in-CTA from ridx (no global OT)
//  - HMMA logits, exp in-register, rowsum, normalize, write norm + Af
// =====================================================================
#define F2_SMA   0                        // A: 8KB (2 ck x [32][128B])
#define F2_SMB   8192                     // B: 2 bufs x 32KB (each: 2 ck x 16KB)
#define F2_RS    (8192 + 65536)           // rs[8][32] = 1KB
#define F2_INV   (F2_RS + 1024)           // inv[32]
#define F2_TOT   (F2_INV + 128)           // 74880 B

__global__ __launch_bounds__(512, 1) void k_fire(
    const float* __restrict__ x,
    const float* __restrict__ centers,
    const float* __restrict__ widths,
    const float* __restrict__ conseq,
    const int*   __restrict__ ridx,
    float* __restrict__ out_norm,
    float* __restrict__ out_xext)
{
    uint32_t sbase = smem_u32(dyn_smem);
    float* rs_sm  = (float*)(dyn_smem + F2_RS);
    float* inv_sm = (float*)(dyn_smem + F2_INV);
    const int t = threadIdx.x;
    const int lane = t & 31;
    const int wid = t >> 5;
    const int warp_m = wid >> 3;          // 0..1 -> rows warp_m*16
    const int warp_n = wid & 7;           // 0..7 -> cols warp_n*16 per chunk
    const int mt = blockIdx.x;

    // ---- side duty: Bc transpose (CTAs 0..15), uses B smem area ----
    if (mt < 16) {
        float* sm = (float*)(dyn_smem + F2_SMB);   // [64][173] = 44288 B
        int r0 = mt * 64;
        for (int idx = t; idx < 64 * NCOLS; idx += 512) {
            int rl = idx / NCOLS, n = idx % NCOLS;
            sm[rl * 173 + n] = conseq[(size_t)(r0 + rl) * NCOLS + n];
        }
        __syncthreads();
        for (int idx = t; idx < NCOLS * 64; idx += 512) {
            int n = idx >> 6, rl = idx & 63;
            float v = sm[rl * 173 + n];
            __half h = __float2half_rn(v);
            g_Bc[(size_t)n * 2048 + r0 + rl] = h;
            g_Bc[(size_t)n * 2048 + 1024 + r0 + rl] =
                __float2half_rn(v - __half2float(h));
        }
        // zero-pad rows n in [170,192) (redundant across 16 CTAs; benign)
        for (int idx = t; idx < 22 * 2048; idx += 512)
            g_Bc[(size_t)170 * 2048 + idx] = __float2half(0.0f);
        __syncthreads();
    }

    // ---- side duty: x_ext rows mt*32..+31 ----
    for (int idx = t; idx < 32 * IEXT; idx += 512) {
        int rl = idx / IEXT, ii = idx % IEXT;
        out_xext[(size_t)(mt * 32 + rl) * IEXT + ii] =
            (ii < DIM) ? x[(size_t)(mt * 32 + rl) * DIM + ii] : 1.0f;
    }

    // ---- build A tile in smem: 2048 half2 (ck0 = zh, ck1 = zl) ----
#pragma unroll
    for (int q = 0; q < 4; q++) {
        int f = t + q * 512;               // 0..2047
        int ck = f >> 10;
        int rem = f & 1023;
        int row = rem >> 5, p = rem & 31;
        int j0 = 2 * p;
        int d = j0 >> 2;
        float xv = x[(size_t)(mt * 32 + row) * DIM + d];
        float c0 = centers[j0],     w0 = widths[j0];
        float c1 = centers[j0 + 1], w1 = widths[j0 + 1];
        float df0 = xv - c0, df1 = xv - c1;
        float z0 = -(df0 * df0) / (2.0f * w0 * w0) + 1e-9f;
        float z1 = -(df1 * df1) / (2.0f * w1 * w1) + 1e-9f;
        __half h0 = __float2half_rn(z0), h1 = __float2half_rn(z1);
        __half2 v;
        if (ck == 0) v = __halves2half2(h0, h1);
        else v = __halves2half2(__float2half_rn(z0 - __half2float(h0)),
                                __float2half_rn(z1 - __half2float(h1)));
        *(__half2*)(dyn_smem + F2_SMA + ck * 4096 + SWZ128(row * 128 + p * 4)) = v;
    }

    // ---- one-hot B builders ----
    const int b_rule = t & 127;
    const int b_seg  = t >> 7;             // 0..3: (ck, j-half)
    const int b_ck   = b_seg >> 1;
    const int b_jb   = (b_seg & 1) * 32;
    int rid[8];
    auto loadRid = [&](int rc) {
        int rbase = rc * 128 + b_rule;
#pragma unroll
        for (int dd = 0; dd < 8; dd++)
            rid[dd] = ridx[(size_t)((b_jb >> 2) + dd) * NRULES + rbase];
    };
    auto storeB = [&](int buf) {
        char* base = dyn_smem + F2_SMB + buf * 32768 + b_ck * 16384;
#pragma unroll
        for (int p = 0; p < 16; p++) {
            int j = b_jb + 2 * p;
            int m = j & 3;
            int rv = rid[p >> 1];
            uint32_t v = ((rv == m) ? 0x3C00u : 0u) |
                         ((rv == m + 1) ? 0x3C000000u : 0u);
            *(uint32_t*)(base + SWZ128(b_rule * 128 + j * 2)) = v;
        }
    };

    loadRid(0);
    storeB(0);
    __syncthreads();

    float eacc[8][2][4];
    float rsum0 = 0.f, rsum1 = 0.f;

#pragma unroll
    for (int rc = 0; rc < 8; rc++) {
        if (rc + 1 < 8) loadRid(rc + 1);   // LDG early, hidden under mma

        uint32_t sBc = sbase + F2_SMB + (rc & 1) * 32768;
        float acc[2][4];
#pragma unroll
        for (int ni = 0; ni < 2; ni++)
#pragma unroll
            for (int qq = 0; qq < 4; qq++) acc[ni][qq] = 0.f;

#pragma unroll
        for (int kk = 0; kk < 8; kk++) {
            uint32_t cka = (kk >> 2) * 4096;
            uint32_t ckb = (kk >> 2) * 16384;
            int kq = kk & 3;
            uint32_t a[4];
            {
                int r = warp_m * 16 + (lane & 15);
                uint32_t off = (uint32_t)(r * 128 + kq * 32 + (lane >> 4) * 16);
                LDSM_X4(a[0], a[1], a[2], a[3], sbase + F2_SMA + cka + SWZ128(off));
            }
            uint32_t b[2][2];
            {
                int r = warp_n * 16 + (lane >> 4) * 8 + (lane & 7);
                uint32_t off = (uint32_t)(r * 128 + kq * 32 + ((lane >> 3) & 1) * 16);
                LDSM_X4(b[0][0], b[0][1], b[1][0], b[1][1], sBc + ckb + SWZ128(off));
            }
            mma16816(acc[0], a, b[0]);
            mma16816(acc[1], a, b[1]);
        }

        if (rc + 1 < 8) storeB((rc + 1) & 1);
        __syncthreads();

#pragma unroll
        for (int ni = 0; ni < 2; ni++) {
            float e0 = __expf(acc[ni][0]), e1 = __expf(acc[ni][1]);
            float e2 = __expf(acc[ni][2]), e3 = __expf(acc[ni][3]);
            eacc[rc][ni][0] = e0; eacc[rc][ni][1] = e1;
            eacc[rc][ni][2] = e2; eacc[rc][ni][3] = e3;
            rsum0 += e0 + e1;
            rsum1 += e2 + e3;
        }
    }

    rsum0 += __shfl_xor_sync(0xffffffffu, rsum0, 1);
    rsum0 += __shfl_xor_sync(0xffffffffu, rsum0, 2);
    rsum1 += __shfl_xor_sync(0xffffffffu, rsum1, 1);
    rsum1 += __shfl_xor_sync(0xffffffffu, rsum1, 2);
    if ((lane & 3) == 0) {
        int rbase = warp_m * 16 + (lane >> 2);
        rs_sm[warp_n * 32 + rbase]     = rsum0;
        rs_sm[warp_n * 32 + rbase + 8] = rsum1;
    }
    __syncthreads();
    if (t < 32) {
        float s = 0.f;
#pragma unroll
        for (int w = 0; w < 8; w++) s += rs_sm[w * 32 + t];
        inv_sm[t] = 1.0f / (s + 1e-9f);
    }
    __syncthreads();

    int rl0 = warp_m * 16 + (lane >> 2);
    float inv0 = inv_sm[rl0];
    float inv1 = inv_sm[rl0 + 8];
    int row0 = mt * 32 + rl0;

#pragma unroll
    for (int rc = 0; rc < 8; rc++)
#pragma unroll
        for (int ni = 0; ni < 2; ni++) {
            int col = rc * 128 + warp_n * 16 + ni * 8 + (lane & 3) * 2;
            float n0 = eacc[rc][ni][0] * inv0, n1 = eacc[rc][ni][1] * inv0;
            float n2 = eacc[rc][ni][2] * inv1, n3 = eacc[rc][ni][3] * inv1;
            *(float2*)(out_norm + (size_t)row0 * NRULES + col) = make_float2(n0, n1);
            *(float2*)(out_norm + (size_t)(row0 + 8) * NRULES + col) = make_float2(n2, n3);
            *(__half2*)(g_Af + (size_t)row0 * NRULES + col) = __floats2half2_rn(n0, n1);
            *(__half2*)(g_Af + (size_t)(row0 + 8) * NRULES + col) = __floats2half2_rn(n2, n3);
        }
}

// =====================================================================
// k_tgemm: HMMA fp16 GEMM (2-pass hi/lo, K_eff=2048), full N=192 tile,
// fused y-contraction epilogue -> g_Yp[ks]. 1 CTA/SM, no reg cap issues.
// CTA 128x192, 256 thr = 8 warps (2M x 4N), warp tile 64x48.
// grid (32 M, 4 Ksplit) = 128 CTAs.
// =====================================================================
#define T_STAGE  40960   // A 16KB @0 + B 24KB @16384
#define T_SMB    16384
#define T_TOT    (2 * T_STAGE)   // 81920

__device__ __forceinline__ void load_chunk(uint32_t sbase, int stage, int mt,
                                           int kg, int t)
{
    const __half* Asrc = g_Af + (size_t)(mt * 128) * NRULES + (kg & 1023);
    const __half* Bsrc = g_Bc + kg;
    uint32_t sA = sbase + stage * T_STAGE;
    uint32_t sB = sA + T_SMB;
#pragma unroll
    for (int i = 0; i < 4; i++) {          // A: 128 rows x 128B
        int f = t + i * 256, row = f >> 3, c = f & 7;
        CP_ASYNC16(sA + SWZ128(row * 128 + c * 16), Asrc + row * NRULES + c * 8);
    }
#pragma unroll
    for (int i = 0; i < 6; i++) {          // B: 192 rows x 128B
        int f = t + i * 256, row = f >> 3, c = f & 7;
        CP_ASYNC16(sB + SWZ128(row * 128 + c * 16), Bsrc + (size_t)row * 2048 + c * 8);
    }
}

__global__ __launch_bounds__(256, 1) void k_tgemm(const float* __restrict__ xext)
{
    uint32_t sbase = smem_u32(dyn_smem);
    const int t = threadIdx.x;
    const int lane = t & 31;
    const int wid = t >> 5;
    const int warp_m = wid >> 2;          // 0..1 -> rows warp_m*64
    const int warp_n = wid & 3;           // 0..3 -> cols warp_n*48
    const int mt = blockIdx.x;
    const int ks = blockIdx.y;

    float acc[4][6][4];
#pragma unroll
    for (int mi = 0; mi < 4; mi++)
#pragma unroll
        for (int ni = 0; ni < 6; ni++)
#pragma unroll
            for (int q = 0; q < 4; q++) acc[mi][ni][q] = 0.f;

    load_chunk(sbase, 0, mt, ks * KLOC, t);
    CP_COMMIT();

    for (int ch = 0; ch < NCH; ch++) {
        if (ch + 1 < NCH) {
            load_chunk(sbase, (ch + 1) & 1, mt, ks * KLOC + (ch + 1) * 64, t);
            CP_COMMIT();
            CP_WAIT1();
        } else {
            CP_WAIT0();
        }
        __syncthreads();

        uint32_t sA = sbase + (ch & 1) * T_STAGE;
        uint32_t sB = sA + T_SMB;

#pragma unroll
        for (int kk = 0; kk < 4; kk++) {
            uint32_t a[4][4];
#pragma unroll
            for (int mi = 0; mi < 4; mi++) {
                int r = warp_m * 64 + mi * 16 + (lane & 15);
                uint32_t off = (uint32_t)(r * 128 + kk * 32 + (lane >> 4) * 16);
                LDSM_X4(a[mi][0], a[mi][1], a[mi][2], a[mi][3], sA + SWZ128(off));
            }
            uint32_t b[6][2];
#pragma unroll
            for (int pr = 0; pr < 3; pr++) {
                int nt8 = 2 * pr + (lane >> 4);
                int r = warp_n * 48 + nt8 * 8 + (lane & 7);
                uint32_t off = (uint32_t)(r * 128 + kk * 32 + ((lane >> 3) & 1) * 16);
                LDSM_X4(b[2 * pr][0], b[2 * pr][1], b[2 * pr + 1][0], b[2 * pr + 1][1],
                        sB + SWZ128(off));
            }
#pragma unroll
            for (int mi = 0; mi < 4; mi++)
#pragma unroll
                for (int ni = 0; ni < 6; ni++)
                    mma16816(acc[mi][ni], a[mi], b[ni]);
        }
        __syncthreads();
    }

    // ---- fused epilogue: two row-halves through Ts, contract -> g_Yp ----
    float* Ts = (float*)dyn_smem;                   // [64][197]  50432 B
    float* xs = (float*)(dyn_smem + 50432);         // [128][17]   8704 B
    float* yh = (float*)(dyn_smem + 50432 + 8704);  // [4][64][10] 10240 B

    for (int f = t; f < 128 * IEXT; f += 256) {
        int rl = f / IEXT, ii = f % IEXT;
        xs[rl * IEXT + ii] = xext[(size_t)(mt * 128 + rl) * IEXT + ii];
    }
    // NOTE: xs region (50432..59136) does not overlap Ts; sync below covers it.

#pragma unroll
    for (int h = 0; h < 2; h++) {
        if (warp_m == h) {
#pragma unroll
            for (int mi = 0; mi < 4; mi++)
#pragma unroll
                for (int ni = 0; ni < 6; ni++) {
                    int lrow = mi * 16 + (lane >> 2);
                    int col = warp_n * 48 + (lane & 3) * 2 + ni * 8;
                    Ts[lrow * 197 + col]           = acc[mi][ni][0];
                    Ts[lrow * 197 + col + 1]       = acc[mi][ni][1];
                    Ts[(lrow + 8) * 197 + col]     = acc[mi][ni][2];
                    Ts[(lrow + 8) * 197 + col + 1] = acc[mi][ni][3];
                }
        }
        __syncthreads();
        {
            int row = t & 63, part = t >> 6;
            const float* tr = Ts + row * 197 + part * 48;
            const float* xr = xs + (h * 64 + row) * IEXT;
            float y[10];
#pragma unroll
            for (int c = 0; c < 10; c++) y[c] = 0.f;
            if      (part == 0) epi_contract<0,   48>(xr, tr, y);
            else if (part == 1) epi_contract<48,  48>(xr, tr, y);
            else if (part == 2) epi_contract<96,  48>(xr, tr, y);
            else                epi_contract<144, 26>(xr, tr, y);
            float* yo = yh + (part * 64 + row) * 10;
#pragma unroll
            for (int c = 0; c < 10; c++) yo[c] = y[c];
        }
        __syncthreads();
        if (t < 64) {
            float* yp = g_Yp + (size_t)ks * (BATCH * NCLS)
                      + (size_t)(mt * 128 + h * 64 + t) * NCLS;
#pragma unroll
            for (int c = 0; c < 10; c++)
                yp[c] = ((yh[t * 10 + c] + yh[(64 + t) * 10 + c]) +
                         yh[(128 + t) * 10 + c]) + yh[(192 + t) * 10 + c];
        }
        __syncthreads();
    }
}

// =====================================================================
// k_yhat: out_y[i] = sum of 4 ks-partials (independent loads).
// =====================================================================
__global__ void k_yhat(float* __restrict__ out_y)
{
    int i = blockIdx.x * 256 + threadIdx.x;
    if (i >= BATCH * NCLS) return;
    float y0 = g_Yp[i];
    float y1 = g_Yp[BATCH * NCLS + i];
    float y2 = g_Yp[2 * BATCH * NCLS + i];
    float y3 = g_Yp[3 * BATCH * NCLS + i];
    out_y[i] = (y0 + y1) + (y2 + y3);
}

// =====================================================================
extern "C" void kernel_launch(void* const* d_in, const int* in_sizes, int n_in,
                              void* d_out, int out_size)
{
    const float* x       = (const float*)d_in[0];
    const float* centers = (const float*)d_in[1];
    const float* widths  = (const float*)d_in[2];
    const float* conseq  = (const float*)d_in[3];
    const int*   ridx    = (const int*)  d_in[4];

    float* out      = (float*)d_out;
    float* out_y    = out;
    float* out_norm = out + BATCH * NCLS;
    float* out_xext = out + BATCH * NCLS + BATCH * NRULES;

    cudaFuncSetAttribute(k_fire,  cudaFuncAttributeMaxDynamicSharedMemorySize, F2_TOT);
    cudaFuncSetAttribute(k_tgemm, cudaFuncAttributeMaxDynamicSharedMemorySize, T_TOT);

    k_fire<<<128, 512, F2_TOT>>>(x, centers, widths, conseq, ridx, out_norm, out_xext);
    k_tgemm<<<dim3(32, 4), 256, T_TOT>>>(out_xext);
    k_yhat<<<160, 256>>>(out_y);
}

// round 16
// speedup vs baseline: 1.1097x; 1.1097x over previous
#include <cuda_runtime.h>
#include <cuda_fp16.h>
#include <cstdint>

#define BATCH   4096
#define DIM     16
#define NRULES  1024
#define NCLS    10
#define IEXT    17
#define NCOLS   170
#define NPAD    192
#define KSPLIT  2
#define KTOT    2048                 // 2 passes x 1024 (ah*bh, ah*bl)
#define KLOC    (KTOT / KSPLIT)      // 1024
#define NCH     (KLOC / 64)          // 16

// single TU-wide dynamic smem symbol
extern __shared__ char dyn_smem[];

// ---------------- static device scratch ----------------
__device__ __half g_Zh[BATCH * 128];      // [b][zh(64)|zl(64)]
__device__ __half g_OTf[NRULES * 128];    // one-hot fp16, [r][j] x2 copies
__device__ __half g_Af[BATCH * NRULES];   // norm_fs fp16 (hi only)
__device__ __half g_Bc[NPAD * 2048];      // [n][ Bh(1024) | Bl(1024) ]
__device__ float  g_Tp[KSPLIT * BATCH * NPAD];   // 6.3 MB partials

// ---------------- helpers ----------------
__device__ __forceinline__ uint32_t smem_u32(const void* p) {
    uint32_t a;
    asm("{ .reg .u64 t; cvta.to.shared.u64 t, %1; cvt.u32.u64 %0, t; }" : "=r"(a) : "l"(p));
    return a;
}
#define SWZ128(o) ((o) ^ (((o) >> 3) & 0x70))

#define CP_ASYNC16(dst, src) \
    asm volatile("cp.async.cg.shared.global [%0], [%1], 16;" :: "r"(dst), "l"(src))
#define CP_COMMIT() asm volatile("cp.async.commit_group;" ::: "memory")
#define CP_WAIT1()  asm volatile("cp.async.wait_group 1;" ::: "memory")
#define CP_WAIT0()  asm volatile("cp.async.wait_group 0;" ::: "memory")

#define LDSM_X4(r0, r1, r2, r3, addr)                                        \
    asm volatile("ldmatrix.sync.aligned.m8n8.x4.shared.b16 {%0,%1,%2,%3}, [%4];" \
        : "=r"(r0), "=r"(r1), "=r"(r2), "=r"(r3) : "r"(addr))

__device__ __forceinline__ void mma16816(float* c, const uint32_t* a, const uint32_t* b) {
    asm volatile(
        "mma.sync.aligned.m16n8k16.row.col.f32.f16.f16.f32 "
        "{%0,%1,%2,%3}, {%4,%5,%6,%7}, {%8,%9}, {%0,%1,%2,%3};"
        : "+f"(c[0]), "+f"(c[1]), "+f"(c[2]), "+f"(c[3])
        : "r"(a[0]), "r"(a[1]), "r"(a[2]), "r"(a[3]), "r"(b[0]), "r"(b[1]));
}

// =====================================================================
// k_prep:
//  blocks [0,16):  Bc transpose tiles via smem (coalesced both ways)
//  blocks [16,..): elementwise regions (OTf, Zh, x_ext, Bc zero-pad)
// =====================================================================
#define PREP_SMEM (64 * 173 * 4)   // 44288 B

__global__ void k_prep(const float* __restrict__ x,
                       const float* __restrict__ centers,
                       const float* __restrict__ widths,
                       const float* __restrict__ conseq,
                       const int*   __restrict__ ridx,
                       float* __restrict__ out_xext)
{
    const int bid = blockIdx.x;
    const int t = threadIdx.x;
    if (bid < 16) {
        float* sm = (float*)dyn_smem;            // [64][173]
        int r0 = bid * 64;
        for (int idx = t; idx < 64 * NCOLS; idx += 256) {
            int rl = idx / NCOLS, n = idx % NCOLS;
            sm[rl * 173 + n] = conseq[(size_t)(r0 + rl) * NCOLS + n];
        }
        __syncthreads();
        for (int idx = t; idx < NCOLS * 64; idx += 256) {
            int n = idx >> 6, rl = idx & 63;
            float v = sm[rl * 173 + n];
            __half h = __float2half_rn(v);
            g_Bc[(size_t)n * 2048 + r0 + rl] = h;
            g_Bc[(size_t)n * 2048 + 1024 + r0 + rl] =
                __float2half_rn(v - __half2float(h));
        }
        return;
    }
    int i = (bid - 16) * 256 + t;
    if (i < 131072) {
        int r = i >> 7, q = i & 127;
        int j = q & 63;
        int d = j >> 2, m = j & 3;
        g_OTf[i] = __float2half((ridx[d * NRULES + r] == m) ? 1.0f : 0.0f);
    } else if (i < 655360) {
        int e = i - 131072;
        int b = e >> 7, j2 = e & 127;
        int j = j2 & 63, lo = j2 >> 6;
        int d = j >> 2;
        float xv = x[b * DIM + d];
        float c  = centers[j];
        float w  = widths[j];
        float df = xv - c;
        float z  = -(df * df) / (2.0f * w * w) + 1e-9f;
        __half h = __float2half_rn(z);
        g_Zh[e] = lo ? __float2half_rn(z - __half2float(h)) : h;
    } else if (i < 724992) {
        int e = i - 655360;
        int b = e / IEXT, ii = e % IEXT;
        out_xext[e] = (ii < DIM) ? x[b * DIM + ii] : 1.0f;
    } else {
        int e = i - 724992;                      // 45056 elems: n in [170,192)
        g_Bc[(size_t)170 * 2048 + e] = __float2half(0.0f);
    }
}

// =====================================================================
// k_fire: fused firing + normalization (R12 version).
// CTA = 32 batch rows x ALL 1024 rules, 512 thr = 16 warps (2M x 8N).
// =====================================================================
#define F2_SMA   0
#define F2_SMB   8192
#define F2_RS    (8192 + 65536)
#define F2_INV   (F2_RS + 1024)
#define F2_TOT   (F2_INV + 128)

__global__ __launch_bounds__(512, 1) void k_fire(float* __restrict__ out_norm)
{
    uint32_t sbase = smem_u32(dyn_smem);
    float* rs_sm  = (float*)(dyn_smem + F2_RS);
    float* inv_sm = (float*)(dyn_smem + F2_INV);
    const int t = threadIdx.x;
    const int lane = t & 31;
    const int wid = t >> 5;
    const int warp_m = wid >> 3;
    const int warp_n = wid & 7;
    const int mt = blockIdx.x;

    uint32_t sA = sbase + F2_SMA;
    uint32_t sB = sbase + F2_SMB;

    {
        int f = t;
        int ck = f >> 8, row = (f >> 3) & 31, c = f & 7;
        CP_ASYNC16(sA + ck * 4096 + SWZ128(row * 128 + c * 16),
                   g_Zh + (size_t)(mt * 32 + row) * 128 + ck * 64 + c * 8);
    }
#pragma unroll
    for (int i = 0; i < 4; i++) {
        int f = t + i * 512;
        int ck = f >> 10, row = (f >> 3) & 127, c = f & 7;
        CP_ASYNC16(sB + ck * 16384 + SWZ128(row * 128 + c * 16),
                   g_OTf + (size_t)row * 128 + ck * 64 + c * 8);
    }
    CP_COMMIT();

    float eacc[8][2][4];
    float rsum0 = 0.f, rsum1 = 0.f;

#pragma unroll
    for (int rc = 0; rc < 8; rc++) {
        CP_WAIT0();
        __syncthreads();
        if (rc + 1 < 8) {
            uint32_t dstg = sB + ((rc + 1) & 1) * 32768;
#pragma unroll
            for (int i = 0; i < 4; i++) {
                int f = t + i * 512;
                int ck = f >> 10, row = (f >> 3) & 127, c = f & 7;
                CP_ASYNC16(dstg + ck * 16384 + SWZ128(row * 128 + c * 16),
                           g_OTf + (size_t)((rc + 1) * 128 + row) * 128 + ck * 64 + c * 8);
            }
            CP_COMMIT();
        }
        uint32_t sBc = sB + (rc & 1) * 32768;

        float acc[2][4];
#pragma unroll
        for (int ni = 0; ni < 2; ni++)
#pragma unroll
            for (int q = 0; q < 4; q++) acc[ni][q] = 0.f;

#pragma unroll
        for (int kk = 0; kk < 8; kk++) {
            uint32_t cka = (kk >> 2) * 4096;
            uint32_t ckb = (kk >> 2) * 16384;
            int kq = kk & 3;
            uint32_t a[4];
            {
                int r = warp_m * 16 + (lane & 15);
                uint32_t off = (uint32_t)(r * 128 + kq * 32 + (lane >> 4) * 16);
                LDSM_X4(a[0], a[1], a[2], a[3], sA + cka + SWZ128(off));
            }
            uint32_t b[2][2];
            {
                int r = warp_n * 16 + (lane >> 4) * 8 + (lane & 7);
                uint32_t off = (uint32_t)(r * 128 + kq * 32 + ((lane >> 3) & 1) * 16);
                LDSM_X4(b[0][0], b[0][1], b[1][0], b[1][1], sBc + ckb + SWZ128(off));
            }
            mma16816(acc[0], a, b[0]);
            mma16816(acc[1], a, b[1]);
        }

#pragma unroll
        for (int ni = 0; ni < 2; ni++) {
            float e0 = __expf(acc[ni][0]), e1 = __expf(acc[ni][1]);
            float e2 = __expf(acc[ni][2]), e3 = __expf(acc[ni][3]);
            eacc[rc][ni][0] = e0; eacc[rc][ni][1] = e1;
            eacc[rc][ni][2] = e2; eacc[rc][ni][3] = e3;
            rsum0 += e0 + e1;
            rsum1 += e2 + e3;
        }
    }

    rsum0 += __shfl_xor_sync(0xffffffffu, rsum0, 1);
    rsum0 += __shfl_xor_sync(0xffffffffu, rsum0, 2);
    rsum1 += __shfl_xor_sync(0xffffffffu, rsum1, 1);
    rsum1 += __shfl_xor_sync(0xffffffffu, rsum1, 2);
    if ((lane & 3) == 0) {
        int rbase = warp_m * 16 + (lane >> 2);
        rs_sm[warp_n * 32 + rbase]     = rsum0;
        rs_sm[warp_n * 32 + rbase + 8] = rsum1;
    }
    __syncthreads();
    if (t < 32) {
        float s = 0.f;
#pragma unroll
        for (int w = 0; w < 8; w++) s += rs_sm[w * 32 + t];
        inv_sm[t] = 1.0f / (s + 1e-9f);
    }
    __syncthreads();

    int rl0 = warp_m * 16 + (lane >> 2);
    float inv0 = inv_sm[rl0];
    float inv1 = inv_sm[rl0 + 8];
    int row0 = mt * 32 + rl0;

#pragma unroll
    for (int rc = 0; rc < 8; rc++)
#pragma unroll
        for (int ni = 0; ni < 2; ni++) {
            int col = rc * 128 + warp_n * 16 + ni * 8 + (lane & 3) * 2;
            float n0 = eacc[rc][ni][0] * inv0, n1 = eacc[rc][ni][1] * inv0;
            float n2 = eacc[rc][ni][2] * inv1, n3 = eacc[rc][ni][3] * inv1;
            *(float2*)(out_norm + (size_t)row0 * NRULES + col) = make_float2(n0, n1);
            *(float2*)(out_norm + (size_t)(row0 + 8) * NRULES + col) = make_float2(n2, n3);
            *(__half2*)(g_Af + (size_t)row0 * NRULES + col) = __floats2half2_rn(n0, n1);
            *(__half2*)(g_Af + (size_t)(row0 + 8) * NRULES + col) = __floats2half2_rn(n2, n3);
        }
}

// =====================================================================
// k_tgemm: HMMA fp16 GEMM, 2-pass hi/lo on B (K_eff=2048).
// CTA 128x96, 256 thr = 8 warps (4M x 2N), warp tile 32x48.
// 3-stage cp.async pipeline (race-safe). grid (32 M, 2 N x 2 Ksplit)=128.
// =====================================================================
#define STAGE_BYTES 28672   // A 16KB + B 12KB
#define SMB_OFF     16384
#define SM_TOT_G    (3 * STAGE_BYTES)

__device__ __forceinline__ void load_chunk(uint32_t sbase, int stage, int mt, int nt,
                                           int kg, int t)
{
    const __half* Asrc = g_Af + (size_t)(mt * 128) * NRULES + (kg & 1023);
    const __half* Bsrc = g_Bc + (size_t)(nt * 96) * 2048 + kg;
    uint32_t sA = sbase + stage * STAGE_BYTES;
    uint32_t sB = sA + SMB_OFF;
#pragma unroll
    for (int i = 0; i < 4; i++) {
        int f = t + i * 256, row = f >> 3, c = f & 7;
        CP_ASYNC16(sA + SWZ128(row * 128 + c * 16), Asrc + row * NRULES + c * 8);
    }
#pragma unroll
    for (int i = 0; i < 3; i++) {
        int f = t + i * 256, row = f >> 3, c = f & 7;
        CP_ASYNC16(sB + SWZ128(row * 128 + c * 16), Bsrc + row * 2048 + c * 8);
    }
}

__global__ __launch_bounds__(256, 2) void k_tgemm()
{
    uint32_t sbase = smem_u32(dyn_smem);
    const int t = threadIdx.x;
    const int lane = t & 31;
    const int wid = t >> 5;
    const int warp_m = wid >> 1;
    const int warp_n = wid & 1;
    const int mt = blockIdx.x;
    const int nt = blockIdx.y & 1;
    const int ks = blockIdx.y >> 1;

    float acc[2][6][4];
#pragma unroll
    for (int mi = 0; mi < 2; mi++)
#pragma unroll
        for (int ni = 0; ni < 6; ni++)
#pragma unroll
            for (int q = 0; q < 4; q++) acc[mi][ni][q] = 0.f;

    load_chunk(sbase, 0, mt, nt, ks * KLOC, t);
    CP_COMMIT();
    load_chunk(sbase, 1, mt, nt, ks * KLOC + 64, t);
    CP_COMMIT();

    for (int ch = 0; ch < NCH; ch++) {
        if (ch + 1 < NCH) { CP_WAIT1(); } else { CP_WAIT0(); }
        __syncthreads();
        if (ch + 2 < NCH) {
            load_chunk(sbase, (ch + 2) % 3, mt, nt, ks * KLOC + (ch + 2) * 64, t);
            CP_COMMIT();
        }

        uint32_t sA = sbase + (ch % 3) * STAGE_BYTES;
        uint32_t sB = sA + SMB_OFF;

#pragma unroll
        for (int kk = 0; kk < 4; kk++) {
            uint32_t a[2][4];
#pragma unroll
            for (int mi = 0; mi < 2; mi++) {
                int r = warp_m * 32 + mi * 16 + (lane & 15);
                uint32_t off = (uint32_t)(r * 128 + kk * 32 + (lane >> 4) * 16);
                LDSM_X4(a[mi][0], a[mi][1], a[mi][2], a[mi][3], sA + SWZ128(off));
            }
            uint32_t b[6][2];
#pragma unroll
            for (int pr = 0; pr < 3; pr++) {
                int nt8 = 2 * pr + (lane >> 4);
                int r = warp_n * 48 + nt8 * 8 + (lane & 7);
                uint32_t off = (uint32_t)(r * 128 + kk * 32 + ((lane >> 3) & 1) * 16);
                LDSM_X4(b[2 * pr][0], b[2 * pr][1], b[2 * pr + 1][0], b[2 * pr + 1][1],
                        sB + SWZ128(off));
            }
#pragma unroll
            for (int mi = 0; mi < 2; mi++)
#pragma unroll
                for (int ni = 0; ni < 6; ni++)
                    mma16816(acc[mi][ni], a[mi], b[ni]);
        }
    }

    float* Tp = g_Tp + (size_t)ks * (BATCH * NPAD);
    int r0 = mt * 128 + warp_m * 32 + (lane >> 2);
    int c0 = nt * 96 + warp_n * 48 + (lane & 3) * 2;
#pragma unroll
    for (int mi = 0; mi < 2; mi++)
#pragma unroll
        for (int ni = 0; ni < 6; ni++) {
            int row = r0 + mi * 16, col = c0 + ni * 8;
            *(float2*)(Tp + (size_t)row * NPAD + col) =
                make_float2(acc[mi][ni][0], acc[mi][ni][1]);
            *(float2*)(Tp + (size_t)(row + 8) * NPAD + col) =
                make_float2(acc[mi][ni][2], acc[mi][ni][3]);
        }
}

// =====================================================================
// k_yhat: block per batch row (192 thr). Coalesced split-K reduction
// (2 slices), scale by xext, smem reduce 17 i-terms per class.
// =====================================================================
__global__ __launch_bounds__(192) void k_yhat(const float* __restrict__ xext,
                                              float* __restrict__ out_y)
{
    __shared__ float sv[NPAD];
    const int b = blockIdx.x;
    const int t = threadIdx.x;            // 0..191 = column

    const float* tb = g_Tp + (size_t)b * NPAD + t;
    float tsum = tb[0] + tb[(size_t)BATCH * NPAD];

    float v = 0.f;
    if (t < NCOLS) v = tsum * xext[b * IEXT + t / NCLS];
    sv[t] = v;
    __syncthreads();

    if (t < NCLS) {
        float y = 0.f;
#pragma unroll
        for (int ii = 0; ii < IEXT; ii++)
            y += sv[ii * NCLS + t];
        out_y[b * NCLS + t] = y;
    }
}

// =====================================================================
extern "C" void kernel_launch(void* const* d_in, const int* in_sizes, int n_in,
                              void* d_out, int out_size)
{
    const float* x       = (const float*)d_in[0];
    const float* centers = (const float*)d_in[1];
    const float* widths  = (const float*)d_in[2];
    const float* conseq  = (const float*)d_in[3];
    const int*   ridx    = (const int*)  d_in[4];

    float* out      = (float*)d_out;
    float* out_y    = out;
    float* out_norm = out + BATCH * NCLS;
    float* out_xext = out + BATCH * NCLS + BATCH * NRULES;

    cudaFuncSetAttribute(k_fire,  cudaFuncAttributeMaxDynamicSharedMemorySize, F2_TOT);
    cudaFuncSetAttribute(k_tgemm, cudaFuncAttributeMaxDynamicSharedMemorySize, SM_TOT_G);

    k_prep<<<3024, 256, PREP_SMEM>>>(x, centers, widths, conseq, ridx, out_xext);
    k_fire<<<128, 512, F2_TOT>>>(out_norm);
    k_tgemm<<<dim3(32, 4), 256, SM_TOT_G>>>();
    k_yhat<<<4096, 192>>>(out_xext, out_y);
}